// round 4
// baseline (speedup 1.0000x reference)
#include <cuda_runtime.h>
#include <math.h>

#define FULL 0xffffffffu

static __device__ __forceinline__ float softplusf(float x) {
    return fmaxf(x, 0.f) + log1pf(expf(-fabsf(x)));
}
static __device__ __forceinline__ float sigmf(float x) {
    return 1.f / (1.f + expf(-x));
}
__host__ __device__ constexpr int TRI(int r, int c) { return r * (r + 1) / 2 + c; }

// =====================================================================
// Kernel 1: mass matrix + Coriolis contribution
//   out[b,i] = (M ddq)_i + Sum_j dq_j (dL_j u + L w_j)_i - w_i . u
// warp-per-element; 8 vectors (h + 7 tangents) pushed through the MLP.
// =====================================================================
__global__ __launch_bounds__(256, 2) void k_mass(
    const float* __restrict__ q, const float* __restrict__ dq, const float* __restrict__ ddq,
    const float* __restrict__ mW1, const float* __restrict__ mb1,
    const float* __restrict__ mW2, const float* __restrict__ mb2,
    const float* __restrict__ mW3, const float* __restrict__ mb3,
    float* __restrict__ out, int batch)
{
    extern __shared__ float sm[];
    float* sW1 = sm;                 // 7*128
    float* sb1 = sW1 + 7 * 128;      // 128
    float* sW2 = sb1 + 128;          // 128*128
    float* sb2 = sW2 + 128 * 128;    // 128
    float* sW3 = sb2 + 128;          // 128*28
    float* sb3 = sW3 + 128 * 28;     // 32 (padded)
    float* sScr = sb3 + 32;          // 8 warps * 224

    const int tid = threadIdx.x;
    for (int i = tid; i < 7 * 128; i += 256) sW1[i] = mW1[i];
    for (int i = tid; i < 128; i += 256) { sb1[i] = mb1[i]; sb2[i] = mb2[i]; }
    for (int i = tid; i < 128 * 128; i += 256) sW2[i] = mW2[i];
    for (int i = tid; i < 128 * 28; i += 256) sW3[i] = mW3[i];
    for (int i = tid; i < 28; i += 256) sb3[i] = mb3[i];
    __syncthreads();

    const int lane = tid & 31;
    const int warp = tid >> 5;
    float* scr = sScr + warp * 224;
    const int gw = blockIdx.x * 8 + warp;
    const int nw = gridDim.x * 8;

    for (int b = gw; b < batch; b += nw) {
        float qv = 0.f, dqv = 0.f, ddqv = 0.f;
        if (lane < 7) { qv = q[b * 7 + lane]; dqv = dq[b * 7 + lane]; ddqv = ddq[b * 7 + lane]; }

        // ---------------- layer 1 + tangents ----------------
        // x[0] = h1, x[1+j] = dh1 for direction j
        float x[8][4];
#pragma unroll
        for (int c = 0; c < 4; c++) {
            const int i = c * 32 + lane;
            float p = sb1[i];
#pragma unroll
            for (int d = 0; d < 7; d++) p += __shfl_sync(FULL, qv, d) * sW1[d * 128 + i];
            const float h = tanhf(p);
            const float g = 1.f - h * h;
            x[0][c] = h;
#pragma unroll
            for (int j = 0; j < 7; j++) x[1 + j][c] = g * sW1[j * 128 + i];
        }

        // ---------------- layer 2 (dominant GEMM) ----------------
        float acc[8][4];
#pragma unroll
        for (int r = 0; r < 4; r++) {
            acc[0][r] = sb2[r * 32 + lane];
#pragma unroll
            for (int v = 1; v < 8; v++) acc[v][r] = 0.f;
        }
#pragma unroll
        for (int cs = 0; cs < 4; cs++) {
#pragma unroll 4
            for (int l = 0; l < 32; l++) {
                const int i = cs * 32 + l;
                float xv[8];
#pragma unroll
                for (int v = 0; v < 8; v++) xv[v] = __shfl_sync(FULL, x[v][cs], l);
                const float* wr = sW2 + i * 128 + lane;
#pragma unroll
                for (int r = 0; r < 4; r++) {
                    const float w = wr[r * 32];
#pragma unroll
                    for (int v = 0; v < 8; v++) acc[v][r] += xv[v] * w;
                }
            }
        }
#pragma unroll
        for (int c = 0; c < 4; c++) {
            const float h = tanhf(acc[0][c]);
            const float g = 1.f - h * h;
            x[0][c] = h;
#pragma unroll
            for (int v = 1; v < 8; v++) x[v][c] = g * acc[v][c];
        }

        // ---------------- layer 3 ----------------
        float a3[8];
        a3[0] = (lane < 28) ? sb3[lane] : 0.f;
#pragma unroll
        for (int v = 1; v < 8; v++) a3[v] = 0.f;
#pragma unroll
        for (int cs = 0; cs < 4; cs++) {
#pragma unroll 4
            for (int l = 0; l < 32; l++) {
                const int i = cs * 32 + l;
                float xv[8];
#pragma unroll
                for (int v = 0; v < 8; v++) xv[v] = __shfl_sync(FULL, x[v][cs], l);
                float w = 0.f;
                if (lane < 28) w = sW3[i * 28 + lane];
#pragma unroll
                for (int v = 0; v < 8; v++) a3[v] += xv[v] * w;
            }
        }
        if (lane < 28) {
#pragma unroll
            for (int v = 0; v < 8; v++) scr[v * 28 + lane] = a3[v];
        }
        __syncwarp();

        // ---------------- Cholesky assembly (O(D^2)) ----------------
        float Lm[28];
#pragma unroll
        for (int t = 0; t < 28; t++) Lm[t] = scr[t];
        float sig[7];
#pragma unroll
        for (int r = 0; r < 7; r++) {
            const int td = TRI(r, r);
            const float p = Lm[td];
            sig[r] = sigmf(p);
            Lm[td] = softplusf(p);
        }
        // lane j (<7) holds dL_j; lanes >= 7 read valid-but-unused data (row 1)
        float dLm[28];
        {
            const int base = (lane < 7) ? (1 + lane) * 28 : 28;
#pragma unroll
            for (int t = 0; t < 28; t++) dLm[t] = scr[base + t];
#pragma unroll
            for (int r = 0; r < 7; r++) dLm[TRI(r, r)] *= sig[r];
        }
        float dqs[7];
#pragma unroll
        for (int r = 0; r < 7; r++) dqs[r] = __shfl_sync(FULL, dqv, r);

        // u = L^T dq, t2 = L^T ddq
        float u[7], t2[7];
#pragma unroll
        for (int c = 0; c < 7; c++) {
            float s = 0.f, s2 = 0.f;
#pragma unroll
            for (int r = 0; r < 7; r++) {
                if (r >= c) {
                    const float lv = Lm[TRI(r, c)];
                    s += lv * dqs[r];
                    s2 += lv * __shfl_sync(FULL, ddqv, r);
                }
            }
            u[c] = s; t2[c] = s2;
        }
        // a = dL_j u ; w = dL_j^T dq  (per lane j)
        float a[7], w[7];
#pragma unroll
        for (int r = 0; r < 7; r++) {
            float s = 0.f;
#pragma unroll
            for (int c = 0; c < 7; c++) if (c <= r) s += dLm[TRI(r, c)] * u[c];
            a[r] = s;
        }
#pragma unroll
        for (int c = 0; c < 7; c++) {
            float s = 0.f;
#pragma unroll
            for (int r = 0; r < 7; r++) if (r >= c) s += dLm[TRI(r, c)] * dqs[r];
            w[c] = s;
        }
        float wu = 0.f;
#pragma unroll
        for (int c = 0; c < 7; c++) wu += w[c] * u[c];

        const float dqj = (lane < 7) ? dqv : 0.f;
        // s1_i = Sum_j dq_j a_j[i]  (butterfly reduce, select at lane i)
        float s1_sel = 0.f;
#pragma unroll
        for (int i = 0; i < 7; i++) {
            float red = dqj * a[i];
#pragma unroll
            for (int off = 16; off > 0; off >>= 1) red += __shfl_xor_sync(FULL, red, off);
            if (lane == i) s1_sel = red;
        }
        // Wred_c = Sum_j dq_j w_j[c]  (all lanes keep it)
        float Wred[7];
#pragma unroll
        for (int c = 0; c < 7; c++) {
            float red = dqj * w[c];
#pragma unroll
            for (int off = 16; off > 0; off >>= 1) red += __shfl_xor_sync(FULL, red, off);
            Wred[c] = red;
        }
        // (L Wred)_i + (L t2)_i, selected per lane i
        float outsel = 0.f;
#pragma unroll
        for (int i = 0; i < 7; i++) {
            float s = 0.f;
#pragma unroll
            for (int c = 0; c <= i; c++) {
                const float lv = Lm[TRI(i, c)];
                s += lv * (Wred[c] + t2[c]);
            }
            if (lane == i) outsel = s;
        }
        if (lane < 7) out[b * 7 + lane] = outsel + s1_sel - wu;
        __syncwarp();
    }
}

// =====================================================================
// Kernel 2: damping + potential gradient, accumulated into out
//   out[b,i] += (L_d (L_d^T dq))_i + gradV_i
// =====================================================================
__global__ __launch_bounds__(256, 2) void k_damp(
    const float* __restrict__ q, const float* __restrict__ dq,
    const float* __restrict__ dW1, const float* __restrict__ db1,
    const float* __restrict__ dW2, const float* __restrict__ db2,
    const float* __restrict__ dW3, const float* __restrict__ db3,
    const float* __restrict__ pW1, const float* __restrict__ pb1,
    const float* __restrict__ pw2,
    float* __restrict__ out, int batch)
{
    extern __shared__ float sm[];
    float* sW1 = sm;                  // 14*128
    float* sb1 = sW1 + 14 * 128;      // 128
    float* sW2 = sb1 + 128;           // 128*128
    float* sb2 = sW2 + 128 * 128;     // 128
    float* sW3 = sb2 + 128;           // 128*28
    float* sb3 = sW3 + 128 * 28;      // 32
    float* spW1 = sb3 + 32;           // 7*128
    float* spb1 = spW1 + 7 * 128;     // 128
    float* sp2 = spb1 + 128;          // 128  (softplus(pw2))
    float* sScr = sp2 + 128;          // 8 warps * 28

    const int tid = threadIdx.x;
    for (int i = tid; i < 14 * 128; i += 256) sW1[i] = dW1[i];
    for (int i = tid; i < 128; i += 256) {
        sb1[i] = db1[i]; sb2[i] = db2[i];
        spb1[i] = pb1[i]; sp2[i] = softplusf(pw2[i]);
    }
    for (int i = tid; i < 128 * 128; i += 256) sW2[i] = dW2[i];
    for (int i = tid; i < 128 * 28; i += 256) sW3[i] = dW3[i];
    for (int i = tid; i < 28; i += 256) sb3[i] = db3[i];
    for (int i = tid; i < 7 * 128; i += 256) spW1[i] = pW1[i];
    __syncthreads();

    const int lane = tid & 31;
    const int warp = tid >> 5;
    float* scr = sScr + warp * 28;
    const int gw = blockIdx.x * 8 + warp;
    const int nw = gridDim.x * 8;

    for (int b = gw; b < batch; b += nw) {
        float xv = 0.f;  // lanes 0..6: q, lanes 7..13: dq
        if (lane < 7) xv = q[b * 7 + lane];
        else if (lane < 14) xv = dq[b * 7 + lane - 7];

        // layer 1
        float h1[4];
#pragma unroll
        for (int c = 0; c < 4; c++) {
            const int i = c * 32 + lane;
            float p = sb1[i];
#pragma unroll
            for (int d = 0; d < 14; d++) p += __shfl_sync(FULL, xv, d) * sW1[d * 128 + i];
            h1[c] = tanhf(p);
        }
        // layer 2
        float acc[4];
#pragma unroll
        for (int r = 0; r < 4; r++) acc[r] = sb2[r * 32 + lane];
#pragma unroll
        for (int cs = 0; cs < 4; cs++) {
#pragma unroll 4
            for (int l = 0; l < 32; l++) {
                const int i = cs * 32 + l;
                const float xb = __shfl_sync(FULL, h1[cs], l);
                const float* wr = sW2 + i * 128 + lane;
#pragma unroll
                for (int r = 0; r < 4; r++) acc[r] += xb * wr[r * 32];
            }
        }
#pragma unroll
        for (int c = 0; c < 4; c++) h1[c] = tanhf(acc[c]);
        // layer 3
        float a3 = (lane < 28) ? sb3[lane] : 0.f;
#pragma unroll
        for (int cs = 0; cs < 4; cs++) {
#pragma unroll 4
            for (int l = 0; l < 32; l++) {
                const int i = cs * 32 + l;
                const float xb = __shfl_sync(FULL, h1[cs], l);
                float w = 0.f;
                if (lane < 28) w = sW3[i * 28 + lane];
                a3 += xb * w;
            }
        }
        if (lane < 28) scr[lane] = a3;
        __syncwarp();

        // gradV: gv_j = Sum_h pW1[j,h] * sigmoid(z_h) * softplus(pw2_h)
        float gp[7];
#pragma unroll
        for (int j = 0; j < 7; j++) gp[j] = 0.f;
#pragma unroll
        for (int c = 0; c < 4; c++) {
            const int i = c * 32 + lane;
            float z = spb1[i];
#pragma unroll
            for (int d = 0; d < 7; d++) z += __shfl_sync(FULL, xv, d) * spW1[d * 128 + i];
            const float s = sigmf(z) * sp2[i];
#pragma unroll
            for (int j = 0; j < 7; j++) gp[j] += spW1[j * 128 + i] * s;
        }
        float gv[7];
#pragma unroll
        for (int j = 0; j < 7; j++) {
            float red = gp[j];
#pragma unroll
            for (int off = 16; off > 0; off >>= 1) red += __shfl_xor_sync(FULL, red, off);
            gv[j] = red;
        }

        // assembly: L_d, u = L^T dq, tau = L u
        float Lm[28];
#pragma unroll
        for (int t = 0; t < 28; t++) Lm[t] = scr[t];
#pragma unroll
        for (int r = 0; r < 7; r++) Lm[TRI(r, r)] = softplusf(Lm[TRI(r, r)]);
        float u[7];
#pragma unroll
        for (int c = 0; c < 7; c++) {
            float s = 0.f;
#pragma unroll
            for (int r = 0; r < 7; r++)
                if (r >= c) s += Lm[TRI(r, c)] * __shfl_sync(FULL, xv, 7 + r);
            u[c] = s;
        }
        float tsel = 0.f;
#pragma unroll
        for (int i = 0; i < 7; i++) {
            float s = 0.f;
#pragma unroll
            for (int c = 0; c <= i; c++) s += Lm[TRI(i, c)] * u[c];
            if (lane == i) tsel = s + gv[i];
        }
        if (lane < 7) {
            const int o = b * 7 + lane;
            out[o] = out[o] + tsel;
        }
        __syncwarp();
    }
}

// =====================================================================
extern "C" void kernel_launch(void* const* d_in, const int* in_sizes, int n_in,
                              void* d_out, int out_size)
{
    const float* q   = (const float*)d_in[0];
    const float* dq  = (const float*)d_in[1];
    const float* ddq = (const float*)d_in[2];
    const float* mW1 = (const float*)d_in[3];
    const float* mb1 = (const float*)d_in[4];
    const float* mW2 = (const float*)d_in[5];
    const float* mb2 = (const float*)d_in[6];
    const float* mW3 = (const float*)d_in[7];
    const float* mb3 = (const float*)d_in[8];
    const float* dW1 = (const float*)d_in[9];
    const float* db1 = (const float*)d_in[10];
    const float* dW2 = (const float*)d_in[11];
    const float* db2 = (const float*)d_in[12];
    const float* dW3 = (const float*)d_in[13];
    const float* db3 = (const float*)d_in[14];
    const float* pW1 = (const float*)d_in[15];
    const float* pb1 = (const float*)d_in[16];
    const float* pw2 = (const float*)d_in[17];
    float* out = (float*)d_out;

    const int batch = in_sizes[0] / 7;

    const size_t sm1 = (size_t)(7*128 + 128 + 128*128 + 128 + 128*28 + 32 + 8*224) * sizeof(float);
    const size_t sm2 = (size_t)(14*128 + 128 + 128*128 + 128 + 128*28 + 32 + 7*128 + 128 + 128 + 8*28) * sizeof(float);

    cudaFuncSetAttribute(k_mass, cudaFuncAttributeMaxDynamicSharedMemorySize, (int)sm1);
    cudaFuncSetAttribute(k_damp, cudaFuncAttributeMaxDynamicSharedMemorySize, (int)sm2);

    k_mass<<<296, 256, sm1>>>(q, dq, ddq, mW1, mb1, mW2, mb2, mW3, mb3, out, batch);
    k_damp<<<296, 256, sm2>>>(q, dq, dW1, db1, dW2, db2, dW3, db3, pW1, pb1, pw2, out, batch);
}

// round 5
// speedup vs baseline: 1.1922x; 1.1922x over previous
#include <cuda_runtime.h>
#include <math.h>

#define FULL 0xffffffffu
typedef unsigned long long ull;

static __device__ __forceinline__ float softplusf(float x) {
    return fmaxf(x, 0.f) + log1pf(expf(-fabsf(x)));
}
static __device__ __forceinline__ float sigmf(float x) {
    return 1.f / (1.f + expf(-x));
}
__host__ __device__ constexpr int TRI(int r, int c) { return r * (r + 1) / 2 + c; }

// ---- packed fp32x2 helpers (sm_100a) ----
static __device__ __forceinline__ ull pack2(float lo, float hi) {
    ull d;
    asm("mov.b64 %0, {%1, %2};" : "=l"(d) : "r"(__float_as_uint(lo)), "r"(__float_as_uint(hi)));
    return d;
}
static __device__ __forceinline__ ull fma2(ull a, ull b, ull c) {
    ull d;
    asm("fma.rn.f32x2 %0, %1, %2, %3;" : "=l"(d) : "l"(a), "l"(b), "l"(c));
    return d;
}
static __device__ __forceinline__ float sum2(ull v) {
    unsigned l, h;
    asm("mov.b64 {%0, %1}, %2;" : "=r"(l), "=r"(h) : "l"(v));
    return __uint_as_float(l) + __uint_as_float(h);
}
static __device__ __forceinline__ float f4c(const float4& v, int j) {
    return j == 0 ? v.x : (j == 1 ? v.y : (j == 2 ? v.z : v.w));
}

// =====================================================================
// Kernel 1: mass + Coriolis. 192 thr (6 warps), warp-per-element,
// f32x2 k-pair packing with per-warp SMEM activation staging.
// =====================================================================
#define M_W1   0
#define M_B1   896
#define M_W2   1024
#define M_B2   17408
#define M_W3   17536
#define M_B3   21120
#define M_STG  21152
#define M_TOT  (21152 + 6 * 1024)

__global__ __launch_bounds__(192, 2) void k_mass(
    const float* __restrict__ q, const float* __restrict__ dq, const float* __restrict__ ddq,
    const float* __restrict__ mW1, const float* __restrict__ mb1,
    const float* __restrict__ mW2, const float* __restrict__ mb2,
    const float* __restrict__ mW3, const float* __restrict__ mb3,
    float* __restrict__ out, int batch)
{
    extern __shared__ float sm[];
    const int tid = threadIdx.x;
    for (int i = tid; i < 7 * 128; i += 192) sm[M_W1 + i] = mW1[i];
    for (int i = tid; i < 128; i += 192) { sm[M_B1 + i] = mb1[i]; sm[M_B2 + i] = mb2[i]; }
    for (int i = tid; i < 128 * 128; i += 192) sm[M_W2 + i] = mW2[i];
    for (int i = tid; i < 128 * 28; i += 192) sm[M_W3 + i] = mW3[i];
    for (int i = tid; i < 32; i += 192) sm[M_B3 + i] = (i < 28) ? mb3[i] : 0.f;
    __syncthreads();

    const int lane = tid & 31;
    const int warp = tid >> 5;
    float* stage = sm + M_STG + warp * 1024;
    const int gw = blockIdx.x * 6 + warp;
    const int nw = gridDim.x * 6;

    for (int b = gw; b < batch; b += nw) {
        float qv = 0.f, dqv = 0.f, ddqv = 0.f;
        if (lane < 7) { qv = q[b * 7 + lane]; dqv = dq[b * 7 + lane]; ddqv = ddq[b * 7 + lane]; }
        float qs[7];
#pragma unroll
        for (int d = 0; d < 7; d++) qs[d] = __shfl_sync(FULL, qv, d);

        // ---- layer 1 + tangents: lane owns outputs 4*lane..4*lane+3 ----
        float x[8][4];
        {
            float4 bq = *(const float4*)&sm[M_B1 + 4 * lane];
            float p[4] = { bq.x, bq.y, bq.z, bq.w };
            float4 w1q[7];
#pragma unroll
            for (int d = 0; d < 7; d++) {
                w1q[d] = *(const float4*)&sm[M_W1 + d * 128 + 4 * lane];
                p[0] = fmaf(qs[d], w1q[d].x, p[0]);
                p[1] = fmaf(qs[d], w1q[d].y, p[1]);
                p[2] = fmaf(qs[d], w1q[d].z, p[2]);
                p[3] = fmaf(qs[d], w1q[d].w, p[3]);
            }
#pragma unroll
            for (int j = 0; j < 4; j++) {
                const float h = tanhf(p[j]);
                const float g = 1.f - h * h;
                x[0][j] = h;
#pragma unroll
                for (int d = 0; d < 7; d++) x[1 + d][j] = g * f4c(w1q[d], j);
            }
        }
        __syncwarp();
#pragma unroll
        for (int v = 0; v < 8; v++)
            *(float4*)&stage[v * 128 + 4 * lane] = make_float4(x[v][0], x[v][1], x[v][2], x[v][3]);
        __syncwarp();

        // ---- layer 2: f32x2 over k-pairs, 4 k per iteration ----
        ull acc[8][4];
#pragma unroll
        for (int v = 0; v < 8; v++)
#pragma unroll
            for (int j = 0; j < 4; j++) acc[v][j] = 0ull;
#pragma unroll 1
        for (int mm = 0; mm < 32; mm++) {
            const int k0 = 4 * mm;
            const float4 wq0 = *(const float4*)&sm[M_W2 + (k0 + 0) * 128 + 4 * lane];
            const float4 wq1 = *(const float4*)&sm[M_W2 + (k0 + 1) * 128 + 4 * lane];
            const float4 wq2 = *(const float4*)&sm[M_W2 + (k0 + 2) * 128 + 4 * lane];
            const float4 wq3 = *(const float4*)&sm[M_W2 + (k0 + 3) * 128 + 4 * lane];
            ull wA[4], wB[4];
#pragma unroll
            for (int j = 0; j < 4; j++) {
                wA[j] = pack2(f4c(wq0, j), f4c(wq1, j));
                wB[j] = pack2(f4c(wq2, j), f4c(wq3, j));
            }
#pragma unroll
            for (int v = 0; v < 8; v++) {
                const double2 xd = *(const double2*)(stage + v * 128 + k0);
                const ull xa = __double_as_longlong(xd.x);
                const ull xb = __double_as_longlong(xd.y);
#pragma unroll
                for (int j = 0; j < 4; j++) {
                    acc[v][j] = fma2(xa, wA[j], acc[v][j]);
                    acc[v][j] = fma2(xb, wB[j], acc[v][j]);
                }
            }
        }
        float y[8][4];
        {
            const float4 b2q = *(const float4*)&sm[M_B2 + 4 * lane];
#pragma unroll
            for (int j = 0; j < 4; j++) {
                const float h = tanhf(sum2(acc[0][j]) + f4c(b2q, j));
                const float g = 1.f - h * h;
                y[0][j] = h;
#pragma unroll
                for (int v = 1; v < 8; v++) y[v][j] = g * sum2(acc[v][j]);
            }
        }
        __syncwarp();
#pragma unroll
        for (int v = 0; v < 8; v++)
            *(float4*)&stage[v * 128 + 4 * lane] = make_float4(y[v][0], y[v][1], y[v][2], y[v][3]);
        __syncwarp();

        // ---- layer 3: f32x2 over k-pairs ----
        ull acc3[8];
#pragma unroll
        for (int v = 0; v < 8; v++) acc3[v] = 0ull;
#pragma unroll 1
        for (int mm = 0; mm < 32; mm++) {
            const int k0 = 4 * mm;
            float w0 = 0.f, w1 = 0.f, w2 = 0.f, w3 = 0.f;
            if (lane < 28) {
                w0 = sm[M_W3 + (k0 + 0) * 28 + lane];
                w1 = sm[M_W3 + (k0 + 1) * 28 + lane];
                w2 = sm[M_W3 + (k0 + 2) * 28 + lane];
                w3 = sm[M_W3 + (k0 + 3) * 28 + lane];
            }
            const ull wp0 = pack2(w0, w1);
            const ull wp1 = pack2(w2, w3);
#pragma unroll
            for (int v = 0; v < 8; v++) {
                const double2 xd = *(const double2*)(stage + v * 128 + k0);
                acc3[v] = fma2(__double_as_longlong(xd.x), wp0, acc3[v]);
                acc3[v] = fma2(__double_as_longlong(xd.y), wp1, acc3[v]);
            }
        }
        float a3[8];
#pragma unroll
        for (int v = 0; v < 8; v++) a3[v] = sum2(acc3[v]);
        if (lane < 28) a3[0] += sm[M_B3 + lane];

        float* scr = stage;   // stage free now; stride-29 scratch (conflict-free)
        __syncwarp();
        if (lane < 28) {
#pragma unroll
            for (int v = 0; v < 8; v++) scr[v * 29 + lane] = a3[v];
        }
        __syncwarp();

        // ---- Cholesky / Coriolis assembly ----
        float Lm[28];
#pragma unroll
        for (int t = 0; t < 28; t++) Lm[t] = scr[t];
        float sig[7];
#pragma unroll
        for (int r = 0; r < 7; r++) {
            const int td = TRI(r, r);
            const float p = Lm[td];
            sig[r] = sigmf(p);
            Lm[td] = softplusf(p);
        }
        float dLm[28];
        {
            const int base = ((lane < 7) ? (1 + lane) : 1) * 29;
#pragma unroll
            for (int t = 0; t < 28; t++) dLm[t] = scr[base + t];
#pragma unroll
            for (int r = 0; r < 7; r++) dLm[TRI(r, r)] *= sig[r];
        }
        float dqs[7], dds[7];
#pragma unroll
        for (int r = 0; r < 7; r++) {
            dqs[r] = __shfl_sync(FULL, dqv, r);
            dds[r] = __shfl_sync(FULL, ddqv, r);
        }
        float u[7], t2[7];
#pragma unroll
        for (int c = 0; c < 7; c++) {
            float s = 0.f, s2 = 0.f;
#pragma unroll
            for (int r = 0; r < 7; r++) {
                if (r >= c) {
                    const float lv = Lm[TRI(r, c)];
                    s = fmaf(lv, dqs[r], s);
                    s2 = fmaf(lv, dds[r], s2);
                }
            }
            u[c] = s; t2[c] = s2;
        }
        float a[7], w[7];
#pragma unroll
        for (int r = 0; r < 7; r++) {
            float s = 0.f;
#pragma unroll
            for (int c = 0; c < 7; c++) if (c <= r) s = fmaf(dLm[TRI(r, c)], u[c], s);
            a[r] = s;
        }
#pragma unroll
        for (int c = 0; c < 7; c++) {
            float s = 0.f;
#pragma unroll
            for (int r = 0; r < 7; r++) if (r >= c) s = fmaf(dLm[TRI(r, c)], dqs[r], s);
            w[c] = s;
        }
        float wu = 0.f;
#pragma unroll
        for (int c = 0; c < 7; c++) wu = fmaf(w[c], u[c], wu);

        const float dqj = (lane < 7) ? dqv : 0.f;
        // group-of-8 butterflies: contributors & consumers all in lanes 0..7
        float s1_sel = 0.f;
#pragma unroll
        for (int i = 0; i < 7; i++) {
            float red = dqj * a[i];
            red += __shfl_xor_sync(FULL, red, 4);
            red += __shfl_xor_sync(FULL, red, 2);
            red += __shfl_xor_sync(FULL, red, 1);
            if (lane == i) s1_sel = red;
        }
        float Wred[7];
#pragma unroll
        for (int c = 0; c < 7; c++) {
            float red = dqj * w[c];
            red += __shfl_xor_sync(FULL, red, 4);
            red += __shfl_xor_sync(FULL, red, 2);
            red += __shfl_xor_sync(FULL, red, 1);
            Wred[c] = red;
        }
        float outsel = 0.f;
#pragma unroll
        for (int i = 0; i < 7; i++) {
            float s = 0.f;
#pragma unroll
            for (int c = 0; c <= i; c++) s = fmaf(Lm[TRI(i, c)], Wred[c] + t2[c], s);
            if (lane == i) outsel = s;
        }
        if (lane < 7) out[b * 7 + lane] = outsel + s1_sel - wu;
        __syncwarp();
    }
}

// =====================================================================
// Kernel 2: damping + potential. Element-per-lane block tiling:
// block = 256 thr processes 32 elements/tile; warps split outputs;
// weights are uniform (broadcast) LDS; f32x2 over k-pairs.
// =====================================================================
#define D_W1T  0         // [i][16]: d0..13 = W1[d][i], [14]=b1[i]
#define D_W2P  2048      // [kpair][i*2+p]  (pair-major for double2 loads)
#define D_B2   18432
#define D_W3P  18560     // [kpair][i*2+p], 64*56
#define D_B3   22144
#define D_PT   22176     // [h][8]: j0..6 = pW1[j][h], [7]=pb1[h]
#define D_SP2  23200
#define D_XIN  23328     // [32][17]
#define D_H1   23872     // [32][130]
#define D_H2   28032     // [32][130]
#define D_A3   32192     // [32][30]
#define D_GVP  33152     // [32][65]
#define D_GV   35232     // [32][8]
#define D_TOT  35488

__global__ __launch_bounds__(256, 1) void k_damp(
    const float* __restrict__ q, const float* __restrict__ dq,
    const float* __restrict__ dW1, const float* __restrict__ db1,
    const float* __restrict__ dW2, const float* __restrict__ db2,
    const float* __restrict__ dW3, const float* __restrict__ db3,
    const float* __restrict__ pW1, const float* __restrict__ pb1,
    const float* __restrict__ pw2,
    float* __restrict__ out, int batch)
{
    extern __shared__ float sm[];
    const int tid = threadIdx.x;
    for (int idx = tid; idx < 2048; idx += 256) {
        const int i = idx >> 4, d = idx & 15;
        float v = 0.f;
        if (d < 14) v = dW1[d * 128 + i];
        else if (d == 14) v = db1[i];
        sm[D_W1T + idx] = v;
    }
    for (int idx = tid; idx < 16384; idx += 256) {
        const int kp = idx >> 8, r = idx & 255;
        sm[D_W2P + idx] = dW2[(2 * kp + (r & 1)) * 128 + (r >> 1)];
    }
    for (int idx = tid; idx < 3584; idx += 256) {
        const int kp = idx / 56, r = idx % 56;
        sm[D_W3P + idx] = dW3[(2 * kp + (r & 1)) * 28 + (r >> 1)];
    }
    for (int idx = tid; idx < 1024; idx += 256) {
        const int h = idx >> 3, j = idx & 7;
        sm[D_PT + idx] = (j < 7) ? pW1[j * 128 + h] : pb1[h];
    }
    for (int idx = tid; idx < 128; idx += 256) {
        sm[D_B2 + idx] = db2[idx];
        sm[D_SP2 + idx] = softplusf(pw2[idx]);
    }
    for (int idx = tid; idx < 32; idx += 256) sm[D_B3 + idx] = (idx < 28) ? db3[idx] : 0.f;
    __syncthreads();

    const int lane = tid & 31;     // element within tile
    const int warp = tid >> 5;     // output-slice owner
    const int ntiles = (batch + 31) >> 5;

    for (int tile = blockIdx.x; tile < ntiles; tile += gridDim.x) {
        const int b0 = tile << 5;
        // ---- stage inputs [e][0..6]=q, [7..13]=dq ----
        for (int idx = tid; idx < 448; idx += 256) {
            const int e = idx / 14, d = idx % 14;
            const int b = b0 + e;
            float v = 0.f;
            if (b < batch) v = (d < 7) ? q[b * 7 + d] : dq[b * 7 + d - 7];
            sm[D_XIN + e * 17 + d] = v;
        }
        __syncthreads();

        float xr[14];
#pragma unroll
        for (int d = 0; d < 14; d++) xr[d] = sm[D_XIN + lane * 17 + d];

        // ---- layer 1: warp owns outputs i in [warp*16, warp*16+16) ----
#pragma unroll
        for (int ii = 0; ii < 16; ii++) {
            const int i = warp * 16 + ii;
            const float4 r0 = *(const float4*)&sm[D_W1T + i * 16];
            const float4 r1 = *(const float4*)&sm[D_W1T + i * 16 + 4];
            const float4 r2 = *(const float4*)&sm[D_W1T + i * 16 + 8];
            const float4 r3 = *(const float4*)&sm[D_W1T + i * 16 + 12];
            float z = r3.z;
            z = fmaf(xr[0], r0.x, z);  z = fmaf(xr[1], r0.y, z);
            z = fmaf(xr[2], r0.z, z);  z = fmaf(xr[3], r0.w, z);
            z = fmaf(xr[4], r1.x, z);  z = fmaf(xr[5], r1.y, z);
            z = fmaf(xr[6], r1.z, z);  z = fmaf(xr[7], r1.w, z);
            z = fmaf(xr[8], r2.x, z);  z = fmaf(xr[9], r2.y, z);
            z = fmaf(xr[10], r2.z, z); z = fmaf(xr[11], r2.w, z);
            z = fmaf(xr[12], r3.x, z); z = fmaf(xr[13], r3.y, z);
            sm[D_H1 + lane * 130 + i] = tanhf(z);
        }
        __syncthreads();

        // ---- layer 2: f32x2 over k-pairs, uniform weight broadcast ----
        {
            ull acc[16];
#pragma unroll
            for (int ii = 0; ii < 16; ii++) acc[ii] = 0ull;
#pragma unroll 2
            for (int kp = 0; kp < 64; kp++) {
                const ull x2 = __double_as_longlong(*(const double*)&sm[D_H1 + lane * 130 + 2 * kp]);
                const float* wrow = &sm[D_W2P + kp * 256 + warp * 32];
#pragma unroll
                for (int m = 0; m < 8; m++) {
                    const double2 wd = *(const double2*)&wrow[4 * m];
                    acc[2 * m]     = fma2(x2, __double_as_longlong(wd.x), acc[2 * m]);
                    acc[2 * m + 1] = fma2(x2, __double_as_longlong(wd.y), acc[2 * m + 1]);
                }
            }
#pragma unroll
            for (int ii = 0; ii < 16; ii++) {
                const int i = warp * 16 + ii;
                sm[D_H2 + lane * 130 + i] = tanhf(sum2(acc[ii]) + sm[D_B2 + i]);
            }
        }
        __syncthreads();

        // ---- layer 3 (warps 0..6, 4 outputs each) ----
        if (warp < 7) {
            ull a4[4] = { 0ull, 0ull, 0ull, 0ull };
#pragma unroll 2
            for (int kp = 0; kp < 64; kp++) {
                const ull x2 = __double_as_longlong(*(const double*)&sm[D_H2 + lane * 130 + 2 * kp]);
                const float* wrow = &sm[D_W3P + kp * 56 + warp * 8];
                const double2 w0 = *(const double2*)&wrow[0];
                const double2 w1 = *(const double2*)&wrow[4];
                a4[0] = fma2(x2, __double_as_longlong(w0.x), a4[0]);
                a4[1] = fma2(x2, __double_as_longlong(w0.y), a4[1]);
                a4[2] = fma2(x2, __double_as_longlong(w1.x), a4[2]);
                a4[3] = fma2(x2, __double_as_longlong(w1.y), a4[3]);
            }
#pragma unroll
            for (int ii = 0; ii < 4; ii++) {
                const int i = warp * 4 + ii;
                sm[D_A3 + lane * 30 + i] = sum2(a4[ii]) + sm[D_B3 + i];
            }
        }
        // ---- gradV: every warp takes a 16-wide h slice ----
        {
            float gp[7] = { 0.f, 0.f, 0.f, 0.f, 0.f, 0.f, 0.f };
            const int h0 = warp * 16;
#pragma unroll
            for (int hh = 0; hh < 16; hh++) {
                const int h = h0 + hh;
                const float4 r0 = *(const float4*)&sm[D_PT + h * 8];
                const float4 r1 = *(const float4*)&sm[D_PT + h * 8 + 4];
                float z = r1.w;
                z = fmaf(xr[0], r0.x, z); z = fmaf(xr[1], r0.y, z);
                z = fmaf(xr[2], r0.z, z); z = fmaf(xr[3], r0.w, z);
                z = fmaf(xr[4], r1.x, z); z = fmaf(xr[5], r1.y, z);
                z = fmaf(xr[6], r1.z, z);
                const float s = sigmf(z) * sm[D_SP2 + h];
                gp[0] = fmaf(r0.x, s, gp[0]); gp[1] = fmaf(r0.y, s, gp[1]);
                gp[2] = fmaf(r0.z, s, gp[2]); gp[3] = fmaf(r0.w, s, gp[3]);
                gp[4] = fmaf(r1.x, s, gp[4]); gp[5] = fmaf(r1.y, s, gp[5]);
                gp[6] = fmaf(r1.z, s, gp[6]);
            }
#pragma unroll
            for (int j = 0; j < 7; j++) sm[D_GVP + lane * 65 + warp * 8 + j] = gp[j];
        }
        __syncthreads();

        // ---- reduce gradV partials across warps ----
        if (tid < 224) {
            const int e = tid / 7, j = tid % 7;
            float s = 0.f;
#pragma unroll
            for (int w = 0; w < 8; w++) s += sm[D_GVP + e * 65 + w * 8 + j];
            sm[D_GV + e * 8 + j] = s;
        }
        __syncthreads();

        // ---- assembly (warp 0; lane = element, all per-lane scalar) ----
        if (warp == 0 && b0 + lane < batch) {
            float Lm[28];
#pragma unroll
            for (int t = 0; t < 28; t++) Lm[t] = sm[D_A3 + lane * 30 + t];
#pragma unroll
            for (int r = 0; r < 7; r++) Lm[TRI(r, r)] = softplusf(Lm[TRI(r, r)]);
            float u[7];
#pragma unroll
            for (int c = 0; c < 7; c++) {
                float s = 0.f;
#pragma unroll
                for (int r = 0; r < 7; r++)
                    if (r >= c) s = fmaf(Lm[TRI(r, c)], xr[7 + r], s);
                u[c] = s;
            }
            const int ob = (b0 + lane) * 7;
#pragma unroll
            for (int i = 0; i < 7; i++) {
                float s = sm[D_GV + lane * 8 + i];
#pragma unroll
                for (int c = 0; c < 7; c++)
                    if (c <= i) s = fmaf(Lm[TRI(i, c)], u[c], s);
                out[ob + i] += s;
            }
        }
        __syncthreads();
    }
}

// =====================================================================
extern "C" void kernel_launch(void* const* d_in, const int* in_sizes, int n_in,
                              void* d_out, int out_size)
{
    const float* q   = (const float*)d_in[0];
    const float* dq  = (const float*)d_in[1];
    const float* ddq = (const float*)d_in[2];
    const float* mW1 = (const float*)d_in[3];
    const float* mb1 = (const float*)d_in[4];
    const float* mW2 = (const float*)d_in[5];
    const float* mb2 = (const float*)d_in[6];
    const float* mW3 = (const float*)d_in[7];
    const float* mb3 = (const float*)d_in[8];
    const float* dW1 = (const float*)d_in[9];
    const float* db1 = (const float*)d_in[10];
    const float* dW2 = (const float*)d_in[11];
    const float* db2 = (const float*)d_in[12];
    const float* dW3 = (const float*)d_in[13];
    const float* db3 = (const float*)d_in[14];
    const float* pW1 = (const float*)d_in[15];
    const float* pb1 = (const float*)d_in[16];
    const float* pw2 = (const float*)d_in[17];
    float* out = (float*)d_out;

    const int batch = in_sizes[0] / 7;

    const size_t sm1 = (size_t)M_TOT * sizeof(float);
    const size_t sm2 = (size_t)D_TOT * sizeof(float);

    cudaFuncSetAttribute(k_mass, cudaFuncAttributeMaxDynamicSharedMemorySize, (int)sm1);
    cudaFuncSetAttribute(k_damp, cudaFuncAttributeMaxDynamicSharedMemorySize, (int)sm2);

    k_mass<<<296, 192, sm1>>>(q, dq, ddq, mW1, mb1, mW2, mb2, mW3, mb3, out, batch);
    k_damp<<<148, 256, sm2>>>(q, dq, dW1, db1, dW2, db2, dW3, db3, pW1, pb1, pw2, out, batch);
}